// round 2
// baseline (speedup 1.0000x reference)
#include <cuda_runtime.h>
#include <math.h>

#define BB   32
#define SS   512
#define HH   512
#define EE   512
#define ROWS 16      // rows per CTA (4 gates x 4 j)
#define JPB  4
#define NTHR 512

// ---------- phase 1 (parallel emb-gates) config ----------
#define TCHUNK 64
#define TBLKS  (SS / TCHUNK)   // 8

// ---------- global scratch ----------
// emb gate contributions: [t][rb(128)][r(16)][b(32)]
__device__ float g_embg[(size_t)SS * 128 * ROWS * BB];
// double-buffered transposed h: [buf][pair(256)][b] as float2 (u64)
__device__ unsigned long long g_ht2[2][256][BB];
// per-producer step flags
__device__ unsigned g_flag[128];

union F2U { unsigned long long u; float2 f; };

__device__ __forceinline__ unsigned long long ffma2u(unsigned long long a,
                                                     unsigned long long b,
                                                     unsigned long long c) {
    unsigned long long d;
    asm("fma.rn.f32x2 %0, %1, %2, %3;" : "=l"(d) : "l"(a), "l"(b), "l"(c));
    return d;
}

__device__ __forceinline__ unsigned ld_acq(const unsigned* p) {
    unsigned v;
    asm volatile("ld.global.acquire.gpu.u32 %0, [%1];" : "=r"(v) : "l"(p) : "memory");
    return v;
}
__device__ __forceinline__ void st_rel(unsigned* p, unsigned v) {
    asm volatile("st.global.release.gpu.u32 [%0], %1;" :: "l"(p), "r"(v) : "memory");
}

__device__ __forceinline__ float sigmoidf_(float x) {
    return 1.0f / (1.0f + expf(-x));
}

// ======================================================================
// Phase 1: emb_gates[t][row][b] = sum_e emb_table[seq[b][t]][e] * W_e[row][e]
// grid (128 rowblocks, TBLKS), 512 threads
// ======================================================================
#define P1_OFF_W    0                      // 16*256 u64 = 32768
#define P1_OFF_PART 32768                  // 16*16*32 u64 = 65536
#define P1_OFF_SEQ  98304                  // 64*32 int = 8192
#define P1_SMEM     (98304 + 8192 + 256)

__global__ __launch_bounds__(NTHR, 1)
void embg_kernel(const int* __restrict__ seq,
                 const float* __restrict__ emb_table,
                 const float* __restrict__ W_ih)
{
    extern __shared__ char smem[];
    unsigned long long* w2_sh  = (unsigned long long*)(smem + P1_OFF_W);
    unsigned long long* part   = (unsigned long long*)(smem + P1_OFF_PART);
    int*                seq_sh = (int*)(smem + P1_OFF_SEQ);

    const int tid = threadIdx.x;
    const int ks  = tid >> 5;    // warp 0..15 : k-split
    const int b   = tid & 31;    // batch lane
    const int rb  = blockIdx.x;  // row block 0..127
    const int t0  = blockIdx.y * TCHUNK;

    // reset phase-2 flags (once per launch; phase 2 runs after this grid ends)
    if (rb == 0 && blockIdx.y == 0 && tid < 128) g_flag[tid] = 0u;

    // stage W_e rows (K elements 0..511 as 256 pairs)
    for (int idx = tid; idx < ROWS * 256; idx += NTHR) {
        int r  = idx >> 8;
        int kp = idx & 255;
        int grow = (r >> 2) * HH + rb * JPB + (r & 3);
        w2_sh[idx] = ((const unsigned long long*)(W_ih + (size_t)grow * (EE + HH)))[kp];
    }
    // stage sequence slice transposed: [t_local][b]
    for (int i = tid; i < TCHUNK * BB; i += NTHR) {
        int tl = i >> 5, bb = i & 31;
        seq_sh[i] = seq[bb * SS + t0 + tl];
    }
    __syncthreads();

    for (int tl = 0; tl < TCHUNK; tl++) {
        int token = seq_sh[tl * BB + b];
        unsigned long long x[16];
        const unsigned long long* er =
            (const unsigned long long*)(emb_table + (size_t)token * EE) + ks * 16;
        #pragma unroll
        for (int i = 0; i < 16; i++) x[i] = er[i];

        unsigned long long acc[ROWS];
        #pragma unroll
        for (int r = 0; r < ROWS; r++) acc[r] = 0ull;

        #pragma unroll
        for (int i2 = 0; i2 < 8; i2++) {
            unsigned long long xa = x[2 * i2], xb = x[2 * i2 + 1];
            #pragma unroll
            for (int r = 0; r < ROWS; r++) {
                ulonglong2 wv = *(const ulonglong2*)(w2_sh + r * 256 + ks * 16 + 2 * i2);
                acc[r] = ffma2u(xa, wv.x, ffma2u(xb, wv.y, acc[r]));
            }
        }
        #pragma unroll
        for (int r = 0; r < ROWS; r++)
            part[(ks * ROWS + r) * BB + b] = acc[r];
        __syncthreads();

        // reduce over 16 k-split warps; warp ks owns row r2 = ks
        {
            float sx = 0.f, sy = 0.f;
            #pragma unroll
            for (int k2 = 0; k2 < 16; k2++) {
                F2U p; p.u = part[(k2 * ROWS + ks) * BB + b];
                sx += p.f.x; sy += p.f.y;
            }
            g_embg[((size_t)(t0 + tl) * 128 + rb) * (ROWS * BB) + ks * BB + b] = sx + sy;
        }
        __syncthreads();
    }
}

// ======================================================================
// Phase 2: sequential LSTM over 512 steps, recurrent half only (K=512)
// grid 128 CTAs, 512 threads; CTA bid owns h[j0..j0+3], j0 = 4*bid
// ======================================================================
#define P2_OFF_W     0         // 16*256 u64 = 32768
#define P2_OFF_PART  32768     // 16*16*32 u64 = 65536
#define P2_OFF_CONST 98304     // 16*32 f = 2048
#define P2_OFF_GSUM  100352    // 16*32 f = 2048
#define P2_OFF_C0    102400    // 4*32 f = 512
#define P2_OFF_HLOC  102912    // 4*32 f = 512
#define P2_SMEM      103680

__global__ __launch_bounds__(NTHR, 1)
void lstm_seq_kernel(const float* __restrict__ enc_h,
                     const float* __restrict__ enc_c,
                     const float* __restrict__ W_ih,
                     const float* __restrict__ W_hh,
                     const float* __restrict__ b_ih,
                     const float* __restrict__ b_hh,
                     float* __restrict__ out)
{
    extern __shared__ char smem[];
    unsigned long long* w2_sh = (unsigned long long*)(smem + P2_OFF_W);
    unsigned long long* part  = (unsigned long long*)(smem + P2_OFF_PART);
    float*              cns_sh = (float*)(smem + P2_OFF_CONST);
    float*              gsum   = (float*)(smem + P2_OFF_GSUM);
    float*              c0_sh  = (float*)(smem + P2_OFF_C0);
    float*              h_loc  = (float*)(smem + P2_OFF_HLOC);

    const int tid = threadIdx.x;
    const int bid = blockIdx.x;
    const int ks  = tid >> 5;
    const int b   = tid & 31;
    const int j0  = bid * JPB;

    // stage W_h rows (K elements 512..1023 -> pairs 256..511 of each W_ih row)
    for (int idx = tid; idx < ROWS * 256; idx += NTHR) {
        int r  = idx >> 8;
        int kp = idx & 255;
        int grow = (r >> 2) * HH + j0 + (r & 3);
        w2_sh[idx] = ((const unsigned long long*)(W_ih + (size_t)grow * (EE + HH)))[256 + kp];
    }
    if (tid < 128) c0_sh[ks * BB + b] = enc_c[b * HH + j0 + ks];
    __syncthreads();

    // const = h0 @ W_hh^T + b_ih + b_hh
    {
        float* partf = (float*)part;
        float h0c[32];
        #pragma unroll
        for (int i = 0; i < 32; i++) h0c[i] = enc_h[b * HH + ks * 32 + i];
        #pragma unroll
        for (int r = 0; r < ROWS; r++) {
            const float* wr = W_hh + (size_t)((r >> 2) * HH + j0 + (r & 3)) * HH + ks * 32;
            float acc = 0.f;
            #pragma unroll
            for (int i = 0; i < 32; i++) acc = fmaf(h0c[i], wr[i], acc);
            partf[(ks * ROWS + r) * BB + b] = acc;
        }
        __syncthreads();
        {
            float s = 0.f;
            #pragma unroll
            for (int k2 = 0; k2 < 16; k2++) s += partf[(k2 * ROWS + ks) * BB + b];
            int grow = (ks >> 2) * HH + j0 + (ks & 3);
            cns_sh[ks * BB + b] = s + b_ih[grow] + b_hh[grow];
        }
        __syncthreads();
    }

    const int pidx = ks * 8 + (b & 7);   // producer CTA this lane polls

    for (int t = 0; t < SS; t++) {
        // emb-gate contribution for this CTA's rows (precomputed in phase 1)
        float embv = __ldcg(&g_embg[((size_t)t * 128 + bid) * (ROWS * BB) + ks * BB + b]);

        unsigned long long x[16];
        if (t > 0) {
            unsigned need = (unsigned)t;
            while (ld_acq(&g_flag[pidx]) < need) { }
            __syncwarp();
            const unsigned long long* hb = &g_ht2[(t - 1) & 1][ks * 16][0];
            #pragma unroll
            for (int i = 0; i < 16; i++) x[i] = __ldcg(&hb[i * BB + b]);
        } else {
            #pragma unroll
            for (int i = 0; i < 16; i++) x[i] = 0ull;
        }

        unsigned long long acc[ROWS];
        #pragma unroll
        for (int r = 0; r < ROWS; r++) acc[r] = 0ull;
        #pragma unroll
        for (int i2 = 0; i2 < 8; i2++) {
            unsigned long long xa = x[2 * i2], xb = x[2 * i2 + 1];
            #pragma unroll
            for (int r = 0; r < ROWS; r++) {
                ulonglong2 wv = *(const ulonglong2*)(w2_sh + r * 256 + ks * 16 + 2 * i2);
                acc[r] = ffma2u(xa, wv.x, ffma2u(xb, wv.y, acc[r]));
            }
        }
        #pragma unroll
        for (int r = 0; r < ROWS; r++)
            part[(ks * ROWS + r) * BB + b] = acc[r];
        __syncthreads();

        // reduce + add const + emb
        {
            float sx = 0.f, sy = 0.f;
            #pragma unroll
            for (int k2 = 0; k2 < 16; k2++) {
                F2U p; p.u = part[(k2 * ROWS + ks) * BB + b];
                sx += p.f.x; sy += p.f.y;
            }
            gsum[ks * BB + b] = sx + sy + cns_sh[ks * BB + b] + embv;
        }
        __syncthreads();

        // gate nonlinearities
        if (tid < 128) {
            int jj = ks;
            float iv = gsum[(0 * 4 + jj) * BB + b];
            float fv = gsum[(1 * 4 + jj) * BB + b];
            float gv = gsum[(2 * 4 + jj) * BB + b];
            float ov = gsum[(3 * 4 + jj) * BB + b];
            float ig = sigmoidf_(iv);
            float fg = sigmoidf_(fv);
            float gg = tanhf(gv);
            float og = sigmoidf_(ov);
            float cc = fg * c0_sh[jj * BB + b] + ig * gg;
            h_loc[jj * BB + b] = og * tanhf(cc);
        }
        __syncthreads();

        // write output + transposed double-buffered h, then fence
        if (tid < 32) {
            float4 o4 = make_float4(h_loc[0 * BB + tid], h_loc[1 * BB + tid],
                                    h_loc[2 * BB + tid], h_loc[3 * BB + tid]);
            *(float4*)(out + (size_t)tid * (SS * HH) + (size_t)t * HH + j0) = o4;
        } else if (tid < 96) {
            int p  = (tid - 32) >> 5;
            int bb = tid & 31;
            F2U hv;
            hv.f = make_float2(h_loc[(2 * p) * BB + bb], h_loc[(2 * p + 1) * BB + bb]);
            g_ht2[t & 1][bid * 2 + p][bb] = hv.u;
            __threadfence();
        }
        __syncthreads();

        // publish
        if (tid == 0) st_rel(&g_flag[bid], (unsigned)(t + 1));
    }
}

extern "C" void kernel_launch(void* const* d_in, const int* in_sizes, int n_in,
                              void* d_out, int out_size) {
    const int*   seq   = (const int*)d_in[0];
    // d_in[1] = enc_out : unused
    const float* enc_h = (const float*)d_in[2];
    const float* enc_c = (const float*)d_in[3];
    const float* emb   = (const float*)d_in[4];
    const float* W_ih  = (const float*)d_in[5];
    const float* W_hh  = (const float*)d_in[6];
    const float* b_ih  = (const float*)d_in[7];
    const float* b_hh  = (const float*)d_in[8];
    float* out = (float*)d_out;

    static bool attr_set = false;
    if (!attr_set) {
        cudaFuncSetAttribute(embg_kernel,
                             cudaFuncAttributeMaxDynamicSharedMemorySize, P1_SMEM);
        cudaFuncSetAttribute(lstm_seq_kernel,
                             cudaFuncAttributeMaxDynamicSharedMemorySize, P2_SMEM);
        attr_set = true;
    }

    dim3 g1(128, TBLKS);
    embg_kernel<<<g1, NTHR, P1_SMEM>>>(seq, emb, W_ih);
    lstm_seq_kernel<<<128, NTHR, P2_SMEM>>>(enc_h, enc_c, W_ih, W_hh,
                                            b_ih, b_hh, out);
}

// round 3
// speedup vs baseline: 1.8817x; 1.8817x over previous
#include <cuda_runtime.h>
#include <math.h>

#define BB   32
#define SS   512
#define HH   512
#define EE   512
#define ROWS 16      // rows per CTA (4 gates x 4 j)
#define JPB  4
#define NTHR 512
#define TCHUNK 64
#define TBLKS  (SS / TCHUNK)   // 8

// ---------- global scratch ----------
__device__ float g_embg[(size_t)SS * 128 * ROWS * BB];   // [t][rb][r][b]
__device__ unsigned long long g_ht2[2][256][BB];          // [buf][kpair][b]
__device__ unsigned g_gen;

union F2U { unsigned long long u; float2 f; };

__device__ __forceinline__ unsigned long long ffma2u(unsigned long long a,
                                                     unsigned long long b,
                                                     unsigned long long c) {
    unsigned long long d;
    asm("fma.rn.f32x2 %0, %1, %2, %3;" : "=l"(d) : "l"(a), "l"(b), "l"(c));
    return d;
}

__device__ __forceinline__ unsigned ld_acq(const unsigned* p) {
    unsigned v;
    asm volatile("ld.global.acquire.gpu.u32 %0, [%1];" : "=r"(v) : "l"(p) : "memory");
    return v;
}

__device__ __forceinline__ float sigmoidf_(float x) {
    return 1.0f / (1.0f + expf(-x));
}

// ======================================================================
// Phase 1: emb_gates (parallel).  grid (128 rowblocks, 8 tblocks) x 512
// ======================================================================
#define P1_OFF_W    0          // 16*256 u64 = 32768
#define P1_OFF_PART 32768      // 16*16*32 f32 = 32768
#define P1_OFF_SEQ  65536      // 64*32 int = 8192
#define P1_SMEM     (65536 + 8192 + 256)

__global__ __launch_bounds__(NTHR, 1)
void embg_kernel(const int* __restrict__ seq,
                 const float* __restrict__ emb_table,
                 const float* __restrict__ W_ih)
{
    extern __shared__ char smem[];
    unsigned long long* w2_sh  = (unsigned long long*)(smem + P1_OFF_W);
    float*              partf  = (float*)(smem + P1_OFF_PART);
    int*                seq_sh = (int*)(smem + P1_OFF_SEQ);

    const int tid = threadIdx.x;
    const int ks  = tid >> 5;
    const int b   = tid & 31;
    const int rb  = blockIdx.x;
    const int t0  = blockIdx.y * TCHUNK;

    if (rb == 0 && blockIdx.y == 0 && tid == 0) g_gen = 0u;   // reset for phase 2

    for (int idx = tid; idx < ROWS * 256; idx += NTHR) {
        int r  = idx >> 8;
        int kp = idx & 255;
        int grow = (r >> 2) * HH + rb * JPB + (r & 3);
        w2_sh[idx] = ((const unsigned long long*)(W_ih + (size_t)grow * (EE + HH)))[kp];
    }
    for (int i = tid; i < TCHUNK * BB; i += NTHR) {
        int tl = i >> 5, bb = i & 31;
        seq_sh[i] = seq[bb * SS + t0 + tl];
    }
    __syncthreads();

    // preload x for tl = 0
    unsigned long long x[16];
    {
        int token = seq_sh[b];
        const unsigned long long* er =
            (const unsigned long long*)(emb_table + (size_t)token * EE) + ks * 16;
        #pragma unroll
        for (int i = 0; i < 16; i++) x[i] = __ldg(&er[i]);
    }

    for (int tl = 0; tl < TCHUNK; tl++) {
        // prefetch next token's embedding slice (hidden behind FMA + reduce)
        unsigned long long xn[16];
        if (tl + 1 < TCHUNK) {
            int token = seq_sh[(tl + 1) * BB + b];
            const unsigned long long* er =
                (const unsigned long long*)(emb_table + (size_t)token * EE) + ks * 16;
            #pragma unroll
            for (int i = 0; i < 16; i++) xn[i] = __ldg(&er[i]);
        }

        unsigned long long acc[ROWS];
        #pragma unroll
        for (int r = 0; r < ROWS; r++) acc[r] = 0ull;
        #pragma unroll
        for (int i2 = 0; i2 < 8; i2++) {
            unsigned long long xa = x[2 * i2], xb = x[2 * i2 + 1];
            #pragma unroll
            for (int r = 0; r < ROWS; r++) {
                ulonglong2 wv = *(const ulonglong2*)(w2_sh + r * 256 + ks * 16 + 2 * i2);
                acc[r] = ffma2u(xa, wv.x, ffma2u(xb, wv.y, acc[r]));
            }
        }
        #pragma unroll
        for (int r = 0; r < ROWS; r++) {
            F2U a; a.u = acc[r];
            partf[(ks * ROWS + r) * BB + b] = a.f.x + a.f.y;
        }
        __syncthreads();
        {
            float s = 0.f;
            #pragma unroll
            for (int k2 = 0; k2 < 16; k2++) s += partf[(k2 * ROWS + ks) * BB + b];
            g_embg[((size_t)(t0 + tl) * 128 + rb) * (ROWS * BB) + ks * BB + b] = s;
        }
        __syncthreads();

        #pragma unroll
        for (int i = 0; i < 16; i++) x[i] = xn[i];
    }
}

// ======================================================================
// Phase 2: sequential LSTM, recurrent half (K=512). 128 CTAs x 512 thr
// ======================================================================
#define P2_OFF_W     0         // 32768
#define P2_OFF_PART  32768     // 16*16*32 f32 = 32768
#define P2_OFF_CONST 65536     // 2048
#define P2_OFF_GSUM  67584     // 2048
#define P2_OFF_C0    69632     // 512
#define P2_SMEM      70400

__global__ __launch_bounds__(NTHR, 1)
void lstm_seq_kernel(const float* __restrict__ enc_h,
                     const float* __restrict__ enc_c,
                     const float* __restrict__ W_ih,
                     const float* __restrict__ W_hh,
                     const float* __restrict__ b_ih,
                     const float* __restrict__ b_hh,
                     float* __restrict__ out)
{
    extern __shared__ char smem[];
    unsigned long long* w2_sh = (unsigned long long*)(smem + P2_OFF_W);
    float*              partf = (float*)(smem + P2_OFF_PART);
    float*              cns_sh = (float*)(smem + P2_OFF_CONST);
    float*              gsum   = (float*)(smem + P2_OFF_GSUM);
    float*              c0_sh  = (float*)(smem + P2_OFF_C0);

    const int tid = threadIdx.x;
    const int bid = blockIdx.x;
    const int ks  = tid >> 5;
    const int b   = tid & 31;
    const int j0  = bid * JPB;

    // stage W_h rows (pairs 256..511 of each W_ih row)
    for (int idx = tid; idx < ROWS * 256; idx += NTHR) {
        int r  = idx >> 8;
        int kp = idx & 255;
        int grow = (r >> 2) * HH + j0 + (r & 3);
        w2_sh[idx] = ((const unsigned long long*)(W_ih + (size_t)grow * (EE + HH)))[256 + kp];
    }
    if (tid < 128) c0_sh[ks * BB + b] = enc_c[b * HH + j0 + ks];
    __syncthreads();

    // const = h0 @ W_hh^T + b_ih + b_hh
    {
        float h0c[32];
        #pragma unroll
        for (int i = 0; i < 32; i++) h0c[i] = enc_h[b * HH + ks * 32 + i];
        #pragma unroll
        for (int r = 0; r < ROWS; r++) {
            const float* wr = W_hh + (size_t)((r >> 2) * HH + j0 + (r & 3)) * HH + ks * 32;
            float acc = 0.f;
            #pragma unroll
            for (int i = 0; i < 32; i++) acc = fmaf(h0c[i], wr[i], acc);
            partf[(ks * ROWS + r) * BB + b] = acc;
        }
        __syncthreads();
        {
            float s = 0.f;
            #pragma unroll
            for (int k2 = 0; k2 < 16; k2++) s += partf[(k2 * ROWS + ks) * BB + b];
            int grow = (ks >> 2) * HH + j0 + (ks & 3);
            cns_sh[ks * BB + b] = s + b_ih[grow] + b_hh[grow];
        }
        __syncthreads();
    }

    for (int t = 0; t < SS; t++) {
        // emb-gate contribution: issue early, independent of h
        float embv = __ldcg(&g_embg[((size_t)t * 128 + bid) * (ROWS * BB) + ks * BB + b]);

        unsigned long long x[16];
        if (t > 0) {
            if (tid == 0) {
                unsigned target = 128u * (unsigned)t;
                while (ld_acq(&g_gen) < target) { }
            }
            __syncthreads();
            const unsigned long long* hb = &g_ht2[(t - 1) & 1][ks * 16][0];
            #pragma unroll
            for (int i = 0; i < 16; i++) x[i] = __ldcg(&hb[i * BB + b]);
        } else {
            #pragma unroll
            for (int i = 0; i < 16; i++) x[i] = 0ull;
        }

        unsigned long long acc[ROWS];
        #pragma unroll
        for (int r = 0; r < ROWS; r++) acc[r] = 0ull;
        #pragma unroll
        for (int i2 = 0; i2 < 8; i2++) {
            unsigned long long xa = x[2 * i2], xb = x[2 * i2 + 1];
            #pragma unroll
            for (int r = 0; r < ROWS; r++) {
                ulonglong2 wv = *(const ulonglong2*)(w2_sh + r * 256 + ks * 16 + 2 * i2);
                acc[r] = ffma2u(xa, wv.x, ffma2u(xb, wv.y, acc[r]));
            }
        }
        #pragma unroll
        for (int r = 0; r < ROWS; r++) {
            F2U a; a.u = acc[r];
            partf[(ks * ROWS + r) * BB + b] = a.f.x + a.f.y;
        }
        __syncthreads();

        {
            float s = 0.f;
            #pragma unroll
            for (int k2 = 0; k2 < 16; k2++) s += partf[(k2 * ROWS + ks) * BB + b];
            gsum[ks * BB + b] = s + cns_sh[ks * BB + b] + embv;
        }
        __syncthreads();

        // nonlinearity + direct stores (threads 0..127: jj x b)
        if (tid < 128) {
            int jj = ks;
            float iv = gsum[(0 * 4 + jj) * BB + b];
            float fv = gsum[(1 * 4 + jj) * BB + b];
            float gv = gsum[(2 * 4 + jj) * BB + b];
            float ov = gsum[(3 * 4 + jj) * BB + b];
            float ig = sigmoidf_(iv);
            float fg = sigmoidf_(fv);
            float gg = tanhf(gv);
            float og = sigmoidf_(ov);
            float cc = fg * c0_sh[jj * BB + b] + ig * gg;
            float hh = og * tanhf(cc);
            out[(size_t)b * (SS * HH) + (size_t)t * HH + j0 + jj] = hh;
            float* hp = (float*)&g_ht2[t & 1][2 * bid + (jj >> 1)][b];
            hp[jj & 1] = hh;
        }
        __syncthreads();

        if (tid == 0) {
            __threadfence();
            atomicAdd(&g_gen, 1u);
        }
    }
}

extern "C" void kernel_launch(void* const* d_in, const int* in_sizes, int n_in,
                              void* d_out, int out_size) {
    const int*   seq   = (const int*)d_in[0];
    // d_in[1] = enc_out : unused
    const float* enc_h = (const float*)d_in[2];
    const float* enc_c = (const float*)d_in[3];
    const float* emb   = (const float*)d_in[4];
    const float* W_ih  = (const float*)d_in[5];
    const float* W_hh  = (const float*)d_in[6];
    const float* b_ih  = (const float*)d_in[7];
    const float* b_hh  = (const float*)d_in[8];
    float* out = (float*)d_out;

    static bool attr_set = false;
    if (!attr_set) {
        cudaFuncSetAttribute(embg_kernel,
                             cudaFuncAttributeMaxDynamicSharedMemorySize, P1_SMEM);
        cudaFuncSetAttribute(lstm_seq_kernel,
                             cudaFuncAttributeMaxDynamicSharedMemorySize, P2_SMEM);
        attr_set = true;
    }

    dim3 g1(128, TBLKS);
    embg_kernel<<<g1, NTHR, P1_SMEM>>>(seq, emb, W_ih);
    lstm_seq_kernel<<<128, NTHR, P2_SMEM>>>(enc_h, enc_c, W_ih, W_hh,
                                            b_ih, b_hh, out);
}

// round 5
// speedup vs baseline: 2.0615x; 1.0955x over previous
#include <cuda_runtime.h>
#include <math.h>

#define BB   32
#define SS   512
#define HH   512
#define EE   512
#define JPB  4
#define NTHR 512
#define TCHUNK 64

// ---------- global scratch ----------
__device__ float g_embg[(size_t)SS * 128 * 16 * BB];   // [t][bid(128)][ks(16)][b(32)]
__device__ unsigned long long g_ht2[2][256][BB];        // [buf][kpair][b]
__device__ unsigned g_flag[128];

union F2U { unsigned long long u; float2 f; };

__device__ __forceinline__ unsigned long long ffma2u(unsigned long long a,
                                                     unsigned long long b,
                                                     unsigned long long c) {
    unsigned long long d;
    asm("fma.rn.f32x2 %0, %1, %2, %3;" : "=l"(d) : "l"(a), "l"(b), "l"(c));
    return d;
}

__device__ __forceinline__ unsigned ld_acq(const unsigned* p) {
    unsigned v;
    asm volatile("ld.global.acquire.gpu.u32 %0, [%1];" : "=r"(v) : "l"(p) : "memory");
    return v;
}
__device__ __forceinline__ void st_rel(unsigned* p, unsigned v) {
    asm volatile("st.global.release.gpu.u32 [%0], %1;" :: "l"(p), "r"(v) : "memory");
}

__device__ __forceinline__ float sigmoidf_(float x) {
    return 1.0f / (1.0f + expf(-x));
}

// ======================================================================
// Phase 1: emb_gates. CTA owns 32 gate rows (8 h-indices), 64 tokens.
// grid (64 rowpairs, 8 tchunks) x 512 threads. Two 16-row passes share x.
// ======================================================================
#define P1_OFF_W    0          // 32 rows * 256 pairs u64 = 65536
#define P1_OFF_PART 65536      // 16 kw * 32 rows * 32 b f32 = 65536
#define P1_OFF_SEQ  131072     // 64*32 int = 8192
#define P1_SMEM     (131072 + 8192 + 256)

__global__ __launch_bounds__(NTHR, 1)
void embg_kernel(const int* __restrict__ seq,
                 const float* __restrict__ emb_table,
                 const float* __restrict__ W_ih)
{
    extern __shared__ char smem[];
    unsigned long long* w2_sh  = (unsigned long long*)(smem + P1_OFF_W);
    float*              partf  = (float*)(smem + P1_OFF_PART);
    int*                seq_sh = (int*)(smem + P1_OFF_SEQ);

    const int tid = threadIdx.x;
    const int ks  = tid >> 5;    // 0..15 k-split warp
    const int b   = tid & 31;    // batch lane
    const int rbp = blockIdx.x;  // rowpair block 0..63 (h-indices 8*rbp..+7)
    const int t0  = blockIdx.y * TCHUNK;

    if (rbp == 0 && blockIdx.y == 0 && tid < 128) g_flag[tid] = 0u;  // reset for phase 2

    // stage 32 rows of W_e (K 0..511 as 256 u64 pairs per row)
    for (int idx = tid; idx < 32 * 256; idx += NTHR) {
        int r  = idx >> 8;            // 0..31
        int kp = idx & 255;
        int grow = (r >> 3) * HH + rbp * 8 + (r & 7);
        w2_sh[idx] = ((const unsigned long long*)(W_ih + (size_t)grow * (EE + HH)))[kp];
    }
    for (int i = tid; i < TCHUNK * BB; i += NTHR) {
        int tl = i >> 5, bb = i & 31;
        seq_sh[i] = seq[bb * SS + t0 + tl];
    }
    __syncthreads();

    // preload x for tl = 0 (this thread's K-chunk of its token's embedding)
    unsigned long long x[16];
    {
        int token = seq_sh[b];
        const unsigned long long* er =
            (const unsigned long long*)(emb_table + (size_t)token * EE) + ks * 16;
        #pragma unroll
        for (int i = 0; i < 16; i++) x[i] = __ldg(&er[i]);
    }

    for (int tl = 0; tl < TCHUNK; tl++) {
        unsigned long long xn[16];
        if (tl + 1 < TCHUNK) {
            int token = seq_sh[(tl + 1) * BB + b];
            const unsigned long long* er =
                (const unsigned long long*)(emb_table + (size_t)token * EE) + ks * 16;
            #pragma unroll
            for (int i = 0; i < 16; i++) xn[i] = __ldg(&er[i]);
        }

        // two passes of 16 rows, sharing x
        #pragma unroll
        for (int p = 0; p < 2; p++) {
            unsigned long long acc[16];
            #pragma unroll
            for (int r = 0; r < 16; r++) acc[r] = 0ull;
            #pragma unroll
            for (int i2 = 0; i2 < 8; i2++) {
                unsigned long long xa = x[2 * i2], xb = x[2 * i2 + 1];
                #pragma unroll
                for (int r = 0; r < 16; r++) {
                    ulonglong2 wv = *(const ulonglong2*)
                        (w2_sh + (p * 16 + r) * 256 + ks * 16 + 2 * i2);
                    acc[r] = ffma2u(xa, wv.x, ffma2u(xb, wv.y, acc[r]));
                }
            }
            #pragma unroll
            for (int r = 0; r < 16; r++) {
                F2U a; a.u = acc[r];
                partf[(ks * 32 + p * 16 + r) * BB + b] = a.f.x + a.f.y;
            }
        }
        __syncthreads();

        // reduce: thread (ks,b) owns local rows ks and ks+16
        #pragma unroll
        for (int p = 0; p < 2; p++) {
            int rr = p * 16 + ks;
            float s = 0.f;
            #pragma unroll
            for (int kw = 0; kw < 16; kw++) s += partf[(kw * 32 + rr) * BB + b];
            int gate = rr >> 3, jj = rr & 7;
            int bid  = 2 * rbp + (jj >> 2);
            int ko   = gate * 4 + (jj & 3);
            g_embg[((size_t)(t0 + tl) * 128 + bid) * (16 * BB) + ko * BB + b] = s;
        }
        __syncthreads();

        #pragma unroll
        for (int i = 0; i < 16; i++) x[i] = xn[i];
    }
}

// ======================================================================
// Phase 2: sequential LSTM, recurrent half (K=512). 128 CTAs x 512 thr
// ======================================================================
#define P2_OFF_W     0         // 16*256 u64 = 32768
#define P2_OFF_PART  32768     // 16*16*32 f32 = 32768
#define P2_OFF_CONST 65536     // 2048
#define P2_OFF_GSUM  67584     // 2048
#define P2_OFF_C0    69632     // 512
#define P2_SMEM      70400

__global__ __launch_bounds__(NTHR, 1)
void lstm_seq_kernel(const float* __restrict__ enc_h,
                     const float* __restrict__ enc_c,
                     const float* __restrict__ W_ih,
                     const float* __restrict__ W_hh,
                     const float* __restrict__ b_ih,
                     const float* __restrict__ b_hh,
                     float* __restrict__ out)
{
    extern __shared__ char smem[];
    unsigned long long* w2_sh = (unsigned long long*)(smem + P2_OFF_W);
    float*              partf = (float*)(smem + P2_OFF_PART);
    float*              cns_sh = (float*)(smem + P2_OFF_CONST);
    float*              gsum   = (float*)(smem + P2_OFF_GSUM);
    float*              c0_sh  = (float*)(smem + P2_OFF_C0);

    const int tid = threadIdx.x;
    const int bid = blockIdx.x;
    const int ks  = tid >> 5;
    const int b   = tid & 31;
    const int j0  = bid * JPB;

    for (int idx = tid; idx < 16 * 256; idx += NTHR) {
        int r  = idx >> 8;
        int kp = idx & 255;
        int grow = (r >> 2) * HH + j0 + (r & 3);
        w2_sh[idx] = ((const unsigned long long*)(W_ih + (size_t)grow * (EE + HH)))[256 + kp];
    }
    if (tid < 128) c0_sh[ks * BB + b] = enc_c[b * HH + j0 + ks];
    __syncthreads();

    // const = h0 @ W_hh^T + b_ih + b_hh
    {
        float h0c[32];
        #pragma unroll
        for (int i = 0; i < 32; i++) h0c[i] = enc_h[b * HH + ks * 32 + i];
        #pragma unroll
        for (int r = 0; r < 16; r++) {
            const float* wr = W_hh + (size_t)((r >> 2) * HH + j0 + (r & 3)) * HH + ks * 32;
            float acc = 0.f;
            #pragma unroll
            for (int i = 0; i < 32; i++) acc = fmaf(h0c[i], wr[i], acc);
            partf[(ks * 16 + r) * BB + b] = acc;
        }
        __syncthreads();
        {
            float s = 0.f;
            #pragma unroll
            for (int k2 = 0; k2 < 16; k2++) s += partf[(k2 * 16 + ks) * BB + b];
            int grow = (ks >> 2) * HH + j0 + (ks & 3);
            cns_sh[ks * BB + b] = s + b_ih[grow] + b_hh[grow];
        }
        __syncthreads();
    }

    for (int t = 0; t < SS; t++) {
        // emb-gate contribution: independent of h, issue before the wait
        float embv = __ldcg(&g_embg[((size_t)t * 128 + bid) * (16 * BB) + ks * BB + b]);

        unsigned long long x[16];
        if (t > 0) {
            if (tid < 128) {
                while (ld_acq(&g_flag[tid]) < (unsigned)t) { }
            }
            __syncthreads();
            const unsigned long long* hb = &g_ht2[(t - 1) & 1][ks * 16][0];
            #pragma unroll
            for (int i = 0; i < 16; i++) x[i] = __ldcg(&hb[i * BB + b]);
        } else {
            #pragma unroll
            for (int i = 0; i < 16; i++) x[i] = 0ull;
        }

        unsigned long long acc[16];
        #pragma unroll
        for (int r = 0; r < 16; r++) acc[r] = 0ull;
        #pragma unroll
        for (int i2 = 0; i2 < 8; i2++) {
            unsigned long long xa = x[2 * i2], xb = x[2 * i2 + 1];
            #pragma unroll
            for (int r = 0; r < 16; r++) {
                ulonglong2 wv = *(const ulonglong2*)(w2_sh + r * 256 + ks * 16 + 2 * i2);
                acc[r] = ffma2u(xa, wv.x, ffma2u(xb, wv.y, acc[r]));
            }
        }
        #pragma unroll
        for (int r = 0; r < 16; r++) {
            F2U a; a.u = acc[r];
            partf[(ks * 16 + r) * BB + b] = a.f.x + a.f.y;
        }
        __syncthreads();

        {
            float s = 0.f;
            #pragma unroll
            for (int k2 = 0; k2 < 16; k2++) s += partf[(k2 * 16 + ks) * BB + b];
            gsum[ks * BB + b] = s + cns_sh[ks * BB + b] + embv;
        }
        __syncthreads();

        // nonlin group (threads 0..127): compute h, store h, publish EARLY,
        // then do the out[] store off the critical path.
        if (tid < 128) {
            int jj = ks;
            float iv = gsum[(0 * 4 + jj) * BB + b];
            float fv = gsum[(1 * 4 + jj) * BB + b];
            float gv = gsum[(2 * 4 + jj) * BB + b];
            float ov = gsum[(3 * 4 + jj) * BB + b];
            float ig = sigmoidf_(iv);
            float fg = sigmoidf_(fv);
            float gg = tanhf(gv);
            float og = sigmoidf_(ov);
            float cc = fg * c0_sh[jj * BB + b] + ig * gg;
            float hh = og * tanhf(cc);
            float* hp = (float*)&g_ht2[t & 1][2 * bid + (jj >> 1)][b];
            hp[jj & 1] = hh;

            asm volatile("bar.sync 1, 128;" ::: "memory");
            if (tid == 0) {
                __threadfence();
                st_rel(&g_flag[bid], (unsigned)(t + 1));
            }
            out[(size_t)b * (SS * HH) + (size_t)t * HH + j0 + jj] = hh;
        }
        __syncthreads();
    }
}

extern "C" void kernel_launch(void* const* d_in, const int* in_sizes, int n_in,
                              void* d_out, int out_size) {
    const int*   seq   = (const int*)d_in[0];
    // d_in[1] = enc_out : unused
    const float* enc_h = (const float*)d_in[2];
    const float* enc_c = (const float*)d_in[3];
    const float* emb   = (const float*)d_in[4];
    const float* W_ih  = (const float*)d_in[5];
    const float* W_hh  = (const float*)d_in[6];
    const float* b_ih  = (const float*)d_in[7];
    const float* b_hh  = (const float*)d_in[8];
    float* out = (float*)d_out;

    static bool attr_set = false;
    if (!attr_set) {
        cudaFuncSetAttribute(embg_kernel,
                             cudaFuncAttributeMaxDynamicSharedMemorySize, P1_SMEM);
        cudaFuncSetAttribute(lstm_seq_kernel,
                             cudaFuncAttributeMaxDynamicSharedMemorySize, P2_SMEM);
        attr_set = true;
    }

    dim3 g1(64, SS / TCHUNK);
    embg_kernel<<<g1, NTHR, P1_SMEM>>>(seq, emb, W_ih);
    lstm_seq_kernel<<<128, NTHR, P2_SMEM>>>(enc_h, enc_c, W_ih, W_hh,
                                            b_ih, b_hh, out);
}